// round 2
// baseline (speedup 1.0000x reference)
#include <cuda_runtime.h>
#include <cuda_bf16.h>
#include <cstdint>

#define NROWS 2048
#define KDIM  4096
#define ODIM  4096
#define WELEMS (ODIM * KDIM)       // 16,777,216
#define XELEMS (NROWS * KDIM)      // 8,388,608

// ---------------- scratch (static device globals; no runtime allocation) ----------
__device__ __align__(16) __nv_bfloat16 g_w_hi[WELEMS];
__device__ __align__(16) __nv_bfloat16 g_w_lo[WELEMS];
__device__ __align__(16) __nv_bfloat16 g_w_var[WELEMS];
__device__ __align__(16) __nv_bfloat16 g_x_hi[XELEMS];
__device__ __align__(16) __nv_bfloat16 g_x_lo[XELEMS];
__device__ __align__(16) __nv_bfloat16 g_x_sq[XELEMS];
__device__ __align__(16) float g_b_mean[ODIM];
__device__ __align__(16) float g_b_var[ODIM];

// ---------------- helpers ----------------------------------------------------------
__device__ __forceinline__ uint32_t smem_u32(const void* p) {
    uint32_t a;
    asm("{ .reg .u64 t; cvta.to.shared.u64 t, %1; cvt.u32.u64 %0, t; }" : "=r"(a) : "l"(p));
    return a;
}
__device__ __forceinline__ void cp16(uint32_t s, const void* g) {
    asm volatile("cp.async.cg.shared.global [%0], [%1], 16;\n" :: "r"(s), "l"(g));
}
#define CP_COMMIT() asm volatile("cp.async.commit_group;" ::: "memory")
#define CP_WAIT1()  asm volatile("cp.async.wait_group 1;" ::: "memory")

__device__ __forceinline__ void ldsm4(uint32_t* r, uint32_t addr) {
    asm volatile("ldmatrix.sync.aligned.m8n8.x4.shared.b16 {%0,%1,%2,%3}, [%4];"
                 : "=r"(r[0]), "=r"(r[1]), "=r"(r[2]), "=r"(r[3]) : "r"(addr));
}
__device__ __forceinline__ void mma16816(float* c, const uint32_t* a, const uint32_t* b) {
    asm volatile(
        "mma.sync.aligned.m16n8k16.row.col.f32.bf16.bf16.f32 "
        "{%0,%1,%2,%3}, {%4,%5,%6,%7}, {%8,%9}, {%0,%1,%2,%3};"
        : "+f"(c[0]), "+f"(c[1]), "+f"(c[2]), "+f"(c[3])
        : "r"(a[0]), "r"(a[1]), "r"(a[2]), "r"(a[3]), "r"(b[0]), "r"(b[1]));
}

// ---------------- prep kernels ----------------------------------------------------
__global__ void __launch_bounds__(256) prep_w_kernel(const float* __restrict__ Wl) {
    size_t i4 = (size_t)blockIdx.x * 256 + threadIdx.x;          // < 4,194,304
    float4 l0 = reinterpret_cast<const float4*>(Wl)[i4];
    float4 l1 = reinterpret_cast<const float4*>(Wl + (size_t)WELEMS)[i4];
    float4 l2 = reinterpret_cast<const float4*>(Wl + 2ull * WELEMS)[i4];
    const float* a0 = reinterpret_cast<const float*>(&l0);
    const float* a1 = reinterpret_cast<const float*>(&l1);
    const float* a2 = reinterpret_cast<const float*>(&l2);
    __nv_bfloat16 hi[4], lo[4], vv[4];
#pragma unroll
    for (int j = 0; j < 4; j++) {
        float e0 = __expf(a0[j]), e1 = __expf(a1[j]), e2 = __expf(a2[j]);
        float inv = __frcp_rn(e0 + e1 + e2);
        float p0 = e0 * inv, p2 = e2 * inv;
        float mean = p2 - p0;
        float var  = (p2 + p0) - mean * mean;
        hi[j] = __float2bfloat16_rn(mean);
        lo[j] = __float2bfloat16_rn(mean - __bfloat162float(hi[j]));
        vv[j] = __float2bfloat16_rn(var);
    }
    __nv_bfloat162* dh = reinterpret_cast<__nv_bfloat162*>(g_w_hi);
    __nv_bfloat162* dl = reinterpret_cast<__nv_bfloat162*>(g_w_lo);
    __nv_bfloat162* dv = reinterpret_cast<__nv_bfloat162*>(g_w_var);
    dh[2 * i4]     = __halves2bfloat162(hi[0], hi[1]);
    dh[2 * i4 + 1] = __halves2bfloat162(hi[2], hi[3]);
    dl[2 * i4]     = __halves2bfloat162(lo[0], lo[1]);
    dl[2 * i4 + 1] = __halves2bfloat162(lo[2], lo[3]);
    dv[2 * i4]     = __halves2bfloat162(vv[0], vv[1]);
    dv[2 * i4 + 1] = __halves2bfloat162(vv[2], vv[3]);
}

__global__ void __launch_bounds__(256) prep_x_kernel(const float* __restrict__ x) {
    size_t i4 = (size_t)blockIdx.x * 256 + threadIdx.x;          // < 2,097,152
    float4 v = reinterpret_cast<const float4*>(x)[i4];
    const float* a = reinterpret_cast<const float*>(&v);
    __nv_bfloat16 hi[4], lo[4], sq[4];
#pragma unroll
    for (int j = 0; j < 4; j++) {
        hi[j] = __float2bfloat16_rn(a[j]);
        lo[j] = __float2bfloat16_rn(a[j] - __bfloat162float(hi[j]));
        sq[j] = __float2bfloat16_rn(a[j] * a[j]);
    }
    __nv_bfloat162* dh = reinterpret_cast<__nv_bfloat162*>(g_x_hi);
    __nv_bfloat162* dl = reinterpret_cast<__nv_bfloat162*>(g_x_lo);
    __nv_bfloat162* ds = reinterpret_cast<__nv_bfloat162*>(g_x_sq);
    dh[2 * i4]     = __halves2bfloat162(hi[0], hi[1]);
    dh[2 * i4 + 1] = __halves2bfloat162(hi[2], hi[3]);
    dl[2 * i4]     = __halves2bfloat162(lo[0], lo[1]);
    dl[2 * i4 + 1] = __halves2bfloat162(lo[2], lo[3]);
    ds[2 * i4]     = __halves2bfloat162(sq[0], sq[1]);
    ds[2 * i4 + 1] = __halves2bfloat162(sq[2], sq[3]);
}

__global__ void __launch_bounds__(256) prep_b_kernel(const float* __restrict__ bl) {
    int o = blockIdx.x * 256 + threadIdx.x;                      // < 4096
    float e0 = __expf(bl[o]);
    float e1 = __expf(bl[ODIM + o]);
    float e2 = __expf(bl[2 * ODIM + o]);
    float inv = __frcp_rn(e0 + e1 + e2);
    float p0 = e0 * inv, p2 = e2 * inv;
    float mean = p2 - p0;
    g_b_mean[o] = mean;
    g_b_var[o]  = (p2 + p0) - mean * mean;
}

// ---------------- GEMM kernel ------------------------------------------------------
// CTA tile: m=128 x o=128, K chunk = 64 bf16. 256 threads (8 warps, 2x4 warp grid,
// warp tile 64m x 32o). 6 smem tiles per stage (xh,xl,xs | wh,wl,wv), 2 stages.
// mma.sync.m16n8k16 bf16 -> fp32. Mean = XH*WH + XH*WL + XL*WH ; Var = XS*WV.
#define TILE_B      16384                     // 128 rows * 128B (64 bf16)
#define STAGE_B     (6 * TILE_B)              // 98304
#define DYN_SMEM    (2 * STAGE_B)             // 196608

__global__ void __launch_bounds__(256, 1) gemm_kernel(float* __restrict__ out) {
    extern __shared__ char smem[];
    uint32_t sb = smem_u32(smem);
    int tid = threadIdx.x, wid = tid >> 5, lane = tid & 31;
    int warp_m = wid & 1;        // 0..1 -> 64-row half
    int warp_n = wid >> 1;       // 0..3 -> 32-col slice
    int m0 = blockIdx.x * 128;
    int o0 = blockIdx.y * 128;

    const __nv_bfloat16* basep[6] = {
        g_x_hi  + (size_t)m0 * KDIM,
        g_x_lo  + (size_t)m0 * KDIM,
        g_x_sq  + (size_t)m0 * KDIM,
        g_w_hi  + (size_t)o0 * KDIM,
        g_w_lo  + (size_t)o0 * KDIM,
        g_w_var + (size_t)o0 * KDIM,
    };

    // ---- cp.async store addressing (per thread, constant) ----
    const int ld_col = tid & 7;          // 16B column
    const int ld_tr  = tid >> 3;         // base row (0..31)
    const uint32_t ld_sw = ((uint32_t)(ld_col * 16)) ^ (((uint32_t)(ld_tr & 7)) << 4);

    auto load_chunk = [&](int chunk, int s) {
        uint32_t sbase = sb + (uint32_t)s * STAGE_B;
        int k0 = chunk * 64;
#pragma unroll
        for (int t = 0; t < 6; t++) {
            const __nv_bfloat16* g = basep[t] + k0 + (size_t)ld_tr * KDIM + ld_col * 8;
            uint32_t tb = sbase + (uint32_t)t * TILE_B + (uint32_t)ld_tr * 128 + ld_sw;
#pragma unroll
            for (int it = 0; it < 4; it++) {
                cp16(tb + it * 32 * 128, g + (size_t)(it * 32) * KDIM);
            }
        }
    };

    // ---- ldmatrix addressing (per lane, constant pieces) ----
    // A (x tiles): 16x16 frag via x4: lanes 0-15 rows 0-15 @k0, lanes 16-31 rows @k+8
    const int a_row = warp_m * 64 + (lane & 15);
    const uint32_t a_rowoff = (uint32_t)a_row * 128;
    const uint32_t a_kb = (uint32_t)((lane >> 4) << 4);
    const uint32_t a_xor = ((uint32_t)(a_row & 7)) << 4;
    // B (w tiles): n16 x k16 via x4: mi=lane>>3; row += (mi&2)<<2 ; kb += (mi&1)<<4
    const int mi = lane >> 3;
    const int b_row = warp_n * 32 + ((mi & 2) << 2) + (lane & 7);
    const uint32_t b_rowoff = (uint32_t)b_row * 128;
    const uint32_t b_kb = (uint32_t)((mi & 1) << 4);
    const uint32_t b_xor = ((uint32_t)(b_row & 7)) << 4;

    float accm[4][4][4];   // [tm][tn8][4]
    float accv[4][4][4];
#pragma unroll
    for (int i = 0; i < 4; i++)
#pragma unroll
        for (int j = 0; j < 4; j++)
#pragma unroll
            for (int r = 0; r < 4; r++) { accm[i][j][r] = 0.f; accv[i][j][r] = 0.f; }

    load_chunk(0, 0); CP_COMMIT();
    load_chunk(1, 1); CP_COMMIT();

    for (int i = 0; i < 64; i++) {
        int s = i & 1;
        CP_WAIT1();
        __syncthreads();

        uint32_t sbase = sb + (uint32_t)s * STAGE_B;
        uint32_t tXH = sbase;
        uint32_t tXL = sbase + TILE_B;
        uint32_t tXS = sbase + 2 * TILE_B;
        uint32_t tWH = sbase + 3 * TILE_B;
        uint32_t tWL = sbase + 4 * TILE_B;
        uint32_t tWV = sbase + 5 * TILE_B;

#pragma unroll
        for (int kk = 0; kk < 4; kk++) {
            uint32_t ak = ((uint32_t)(kk * 32) + a_kb) ^ a_xor;
            uint32_t bk = ((uint32_t)(kk * 32) + b_kb) ^ b_xor;
            uint32_t wh[8], wl[8], wv[8];
#pragma unroll
            for (int tn = 0; tn < 2; tn++) {
                uint32_t ro = b_rowoff + (uint32_t)(tn * 16 * 128) + bk;
                ldsm4(wh + tn * 4, tWH + ro);
                ldsm4(wl + tn * 4, tWL + ro);
                ldsm4(wv + tn * 4, tWV + ro);
            }
#pragma unroll
            for (int tm = 0; tm < 4; tm++) {
                uint32_t ro = a_rowoff + (uint32_t)(tm * 16 * 128) + ak;
                uint32_t xh[4], xl[4], xs[4];
                ldsm4(xh, tXH + ro);
                ldsm4(xl, tXL + ro);
                ldsm4(xs, tXS + ro);
#pragma unroll
                for (int tn8 = 0; tn8 < 4; tn8++) {
                    const uint32_t* bh = &wh[(tn8 >> 1) * 4 + (tn8 & 1) * 2];
                    const uint32_t* blr = &wl[(tn8 >> 1) * 4 + (tn8 & 1) * 2];
                    const uint32_t* bv = &wv[(tn8 >> 1) * 4 + (tn8 & 1) * 2];
                    mma16816(accm[tm][tn8], xh, bh);
                    mma16816(accm[tm][tn8], xh, blr);
                    mma16816(accm[tm][tn8], xl, bh);
                    mma16816(accv[tm][tn8], xs, bv);
                }
            }
        }

        __syncthreads();
        if (i + 2 < 64) load_chunk(i + 2, s);
        CP_COMMIT();
    }

    // ---------------- epilogue ----------------
    int ob = o0 + warp_n * 32 + 2 * (lane & 3);
    float2 bm2[4], bv2[4];
#pragma unroll
    for (int tn8 = 0; tn8 < 4; tn8++) {
        bm2[tn8] = *reinterpret_cast<const float2*>(&g_b_mean[ob + tn8 * 8]);
        bv2[tn8] = *reinterpret_cast<const float2*>(&g_b_var[ob + tn8 * 8]);
    }
    int mrow = m0 + warp_m * 64 + (lane >> 2);
#pragma unroll
    for (int tm = 0; tm < 4; tm++) {
        size_t r0 = (size_t)(mrow + tm * 16) * (2 * ODIM);
        size_t r8 = (size_t)(mrow + tm * 16 + 8) * (2 * ODIM);
#pragma unroll
        for (int tn8 = 0; tn8 < 4; tn8++) {
            int oc = ob + tn8 * 8;
            float2 v;
            v.x = accm[tm][tn8][0] + bm2[tn8].x;
            v.y = accm[tm][tn8][1] + bm2[tn8].y;
            *reinterpret_cast<float2*>(out + r0 + oc) = v;
            v.x = accm[tm][tn8][2] + bm2[tn8].x;
            v.y = accm[tm][tn8][3] + bm2[tn8].y;
            *reinterpret_cast<float2*>(out + r8 + oc) = v;
            v.x = accv[tm][tn8][0] + bv2[tn8].x;
            v.y = accv[tm][tn8][1] + bv2[tn8].y;
            *reinterpret_cast<float2*>(out + r0 + ODIM + oc) = v;
            v.x = accv[tm][tn8][2] + bv2[tn8].x;
            v.y = accv[tm][tn8][3] + bv2[tn8].y;
            *reinterpret_cast<float2*>(out + r8 + ODIM + oc) = v;
        }
    }
}

// ---------------- launch -----------------------------------------------------------
extern "C" void kernel_launch(void* const* d_in, const int* in_sizes, int n_in,
                              void* d_out, int out_size) {
    (void)in_sizes; (void)n_in; (void)out_size;
    const float* x  = (const float*)d_in[0];
    const float* Wl = (const float*)d_in[1];
    const float* bl = (const float*)d_in[2];
    float* out = (float*)d_out;

    prep_w_kernel<<<WELEMS / 4 / 256, 256>>>(Wl);   // 16384 blocks
    prep_x_kernel<<<XELEMS / 4 / 256, 256>>>(x);    // 8192 blocks
    prep_b_kernel<<<ODIM / 256, 256>>>(bl);         // 16 blocks

    cudaFuncSetAttribute(gemm_kernel, cudaFuncAttributeMaxDynamicSharedMemorySize, DYN_SMEM);
    gemm_kernel<<<dim3(NROWS / 128, ODIM / 128, 1), 256, DYN_SMEM>>>(out);
}

// round 4
// speedup vs baseline: 1.6616x; 1.6616x over previous
#include <cuda_runtime.h>
#include <cuda_fp16.h>
#include <cstdint>

#define NROWS 2048
#define KDIM  4096
#define ODIM  4096
#define WELEMS (ODIM * KDIM)       // 16,777,216
#define XELEMS (NROWS * KDIM)      // 8,388,608

// ---------------- scratch (static device globals; no runtime allocation) ----------
__device__ __align__(16) __half g_w_m[WELEMS];
__device__ __align__(16) __half g_w_v[WELEMS];
__device__ __align__(16) __half g_x[XELEMS];
__device__ __align__(16) __half g_x_sq[XELEMS];
__device__ __align__(16) float g_b_mean[ODIM];
__device__ __align__(16) float g_b_var[ODIM];

// ---------------- helpers ----------------------------------------------------------
__device__ __forceinline__ uint32_t smem_u32(const void* p) {
    uint32_t a;
    asm("{ .reg .u64 t; cvta.to.shared.u64 t, %1; cvt.u32.u64 %0, t; }" : "=r"(a) : "l"(p));
    return a;
}
__device__ __forceinline__ void cp16(uint32_t s, const void* g) {
    asm volatile("cp.async.cg.shared.global [%0], [%1], 16;\n" :: "r"(s), "l"(g));
}
#define CP_COMMIT() asm volatile("cp.async.commit_group;" ::: "memory")
#define CP_WAIT1()  asm volatile("cp.async.wait_group 1;" ::: "memory")

__device__ __forceinline__ void ldsm4(uint32_t* r, uint32_t addr) {
    asm volatile("ldmatrix.sync.aligned.m8n8.x4.shared.b16 {%0,%1,%2,%3}, [%4];"
                 : "=r"(r[0]), "=r"(r[1]), "=r"(r[2]), "=r"(r[3]) : "r"(addr));
}
__device__ __forceinline__ void mma16816(float* c, const uint32_t* a, const uint32_t* b) {
    asm volatile(
        "mma.sync.aligned.m16n8k16.row.col.f32.f16.f16.f32 "
        "{%0,%1,%2,%3}, {%4,%5,%6,%7}, {%8,%9}, {%0,%1,%2,%3};"
        : "+f"(c[0]), "+f"(c[1]), "+f"(c[2]), "+f"(c[3])
        : "r"(a[0]), "r"(a[1]), "r"(a[2]), "r"(a[3]), "r"(b[0]), "r"(b[1]));
}

// ---------------- prep kernels ----------------------------------------------------
__global__ void __launch_bounds__(256) prep_w_kernel(const float* __restrict__ Wl) {
    size_t i4 = (size_t)blockIdx.x * 256 + threadIdx.x;          // < 4,194,304
    float4 l0 = reinterpret_cast<const float4*>(Wl)[i4];
    float4 l1 = reinterpret_cast<const float4*>(Wl + (size_t)WELEMS)[i4];
    float4 l2 = reinterpret_cast<const float4*>(Wl + 2ull * WELEMS)[i4];
    const float* a0 = reinterpret_cast<const float*>(&l0);
    const float* a1 = reinterpret_cast<const float*>(&l1);
    const float* a2 = reinterpret_cast<const float*>(&l2);
    __half m[4], v[4];
#pragma unroll
    for (int j = 0; j < 4; j++) {
        float e0 = __expf(a0[j]), e1 = __expf(a1[j]), e2 = __expf(a2[j]);
        float inv = __frcp_rn(e0 + e1 + e2);
        float p0 = e0 * inv, p2 = e2 * inv;
        float mean = p2 - p0;
        float var  = (p2 + p0) - mean * mean;
        m[j] = __float2half_rn(mean);
        v[j] = __float2half_rn(var);
    }
    __half2* dm = reinterpret_cast<__half2*>(g_w_m);
    __half2* dv = reinterpret_cast<__half2*>(g_w_v);
    dm[2 * i4]     = __halves2half2(m[0], m[1]);
    dm[2 * i4 + 1] = __halves2half2(m[2], m[3]);
    dv[2 * i4]     = __halves2half2(v[0], v[1]);
    dv[2 * i4 + 1] = __halves2half2(v[2], v[3]);
}

__global__ void __launch_bounds__(256) prep_x_kernel(const float* __restrict__ x) {
    size_t i4 = (size_t)blockIdx.x * 256 + threadIdx.x;          // < 2,097,152
    float4 v = reinterpret_cast<const float4*>(x)[i4];
    const float* a = reinterpret_cast<const float*>(&v);
    __half h[4], s[4];
#pragma unroll
    for (int j = 0; j < 4; j++) {
        h[j] = __float2half_rn(a[j]);
        s[j] = __float2half_rn(a[j] * a[j]);
    }
    __half2* dh = reinterpret_cast<__half2*>(g_x);
    __half2* ds = reinterpret_cast<__half2*>(g_x_sq);
    dh[2 * i4]     = __halves2half2(h[0], h[1]);
    dh[2 * i4 + 1] = __halves2half2(h[2], h[3]);
    ds[2 * i4]     = __halves2half2(s[0], s[1]);
    ds[2 * i4 + 1] = __halves2half2(s[2], s[3]);
}

__global__ void __launch_bounds__(256) prep_b_kernel(const float* __restrict__ bl) {
    int o = blockIdx.x * 256 + threadIdx.x;                      // < 4096
    float e0 = __expf(bl[o]);
    float e1 = __expf(bl[ODIM + o]);
    float e2 = __expf(bl[2 * ODIM + o]);
    float inv = __frcp_rn(e0 + e1 + e2);
    float p0 = e0 * inv, p2 = e2 * inv;
    float mean = p2 - p0;
    g_b_mean[o] = mean;
    g_b_var[o]  = (p2 + p0) - mean * mean;
}

// ---------------- GEMM kernel ------------------------------------------------------
// CTA tile: m=128 x o=128, K chunk = 64 fp16. 256 threads (8 warps, 2x4 warp grid,
// warp tile 64m x 32o). 4 smem tiles per stage (x, xsq | wm, wv), 3 stages,
// single __syncthreads per chunk. mma.sync.m16n8k16 f16 -> fp32.
// Mean = X*WM ; Var = XSQ*WV.
#define TILE_B      16384                     // 128 rows * 128B (64 fp16)
#define STAGE_B     (4 * TILE_B)              // 65536
#define DYN_SMEM    (3 * STAGE_B)             // 196608

__global__ void __launch_bounds__(256, 1) gemm_kernel(float* __restrict__ out) {
    extern __shared__ char smem[];
    uint32_t sb = smem_u32(smem);
    int tid = threadIdx.x, wid = tid >> 5, lane = tid & 31;
    int warp_m = wid & 1;        // 0..1 -> 64-row half
    int warp_n = wid >> 1;       // 0..3 -> 32-col slice
    int m0 = blockIdx.x * 128;   // m fastest -> concurrent CTAs share w tiles in L2
    int o0 = blockIdx.y * 128;

    const __half* basep[4] = {
        g_x    + (size_t)m0 * KDIM,
        g_x_sq + (size_t)m0 * KDIM,
        g_w_m  + (size_t)o0 * KDIM,
        g_w_v  + (size_t)o0 * KDIM,
    };

    // ---- cp.async store addressing (per thread, constant) ----
    const int ld_col = tid & 7;          // 16B column
    const int ld_tr  = tid >> 3;         // base row (0..31)
    const uint32_t ld_sw = ((uint32_t)(ld_col * 16)) ^ (((uint32_t)(ld_tr & 7)) << 4);

    auto load_chunk = [&](int chunk, int s) {
        uint32_t sbase = sb + (uint32_t)s * STAGE_B;
        int k0 = chunk * 64;
#pragma unroll
        for (int t = 0; t < 4; t++) {
            const __half* g = basep[t] + k0 + (size_t)ld_tr * KDIM + ld_col * 8;
            uint32_t tb = sbase + (uint32_t)t * TILE_B + (uint32_t)ld_tr * 128 + ld_sw;
#pragma unroll
            for (int it = 0; it < 4; it++) {
                cp16(tb + it * 32 * 128, g + (size_t)(it * 32) * KDIM);
            }
        }
    };

    // ---- ldmatrix addressing (per lane, constant pieces) ----
    const int a_row = warp_m * 64 + (lane & 15);
    const uint32_t a_rowoff = (uint32_t)a_row * 128;
    const uint32_t a_kb = (uint32_t)((lane >> 4) << 4);
    const uint32_t a_xor = ((uint32_t)(a_row & 7)) << 4;
    const int mi = lane >> 3;
    const int b_row = warp_n * 32 + ((mi & 2) << 2) + (lane & 7);
    const uint32_t b_rowoff = (uint32_t)b_row * 128;
    const uint32_t b_kb = (uint32_t)((mi & 1) << 4);
    const uint32_t b_xor = ((uint32_t)(b_row & 7)) << 4;

    float accm[4][4][4];   // [tm][tn8][4]
    float accv[4][4][4];
#pragma unroll
    for (int i = 0; i < 4; i++)
#pragma unroll
        for (int j = 0; j < 4; j++)
#pragma unroll
            for (int r = 0; r < 4; r++) { accm[i][j][r] = 0.f; accv[i][j][r] = 0.f; }

    load_chunk(0, 0); CP_COMMIT();
    load_chunk(1, 1); CP_COMMIT();

    for (int i = 0; i < 64; i++) {
        int s = i % 3;
        CP_WAIT1();                      // chunk i resident (group i+1 may be in flight)
        __syncthreads();                 // orders compute(i-1) before load(i+2) below

        if (i + 2 < 64) load_chunk(i + 2, (i + 2) % 3);
        CP_COMMIT();                     // always commit (empty at tail keeps accounting)

        uint32_t sbase = sb + (uint32_t)s * STAGE_B;
        uint32_t tX  = sbase;
        uint32_t tXS = sbase + TILE_B;
        uint32_t tWM = sbase + 2 * TILE_B;
        uint32_t tWV = sbase + 3 * TILE_B;

#pragma unroll
        for (int kk = 0; kk < 4; kk++) {
            uint32_t ak = ((uint32_t)(kk * 32) + a_kb) ^ a_xor;
            uint32_t bk = ((uint32_t)(kk * 32) + b_kb) ^ b_xor;
            uint32_t wm[8], wv[8];
#pragma unroll
            for (int tn = 0; tn < 2; tn++) {
                uint32_t ro = b_rowoff + (uint32_t)(tn * 16 * 128) + bk;
                ldsm4(wm + tn * 4, tWM + ro);
                ldsm4(wv + tn * 4, tWV + ro);
            }
#pragma unroll
            for (int tm = 0; tm < 4; tm++) {
                uint32_t ro = a_rowoff + (uint32_t)(tm * 16 * 128) + ak;
                uint32_t xf[4], xs[4];
                ldsm4(xf, tX + ro);
                ldsm4(xs, tXS + ro);
#pragma unroll
                for (int tn8 = 0; tn8 < 4; tn8++) {
                    const uint32_t* bm = &wm[(tn8 >> 1) * 4 + (tn8 & 1) * 2];
                    const uint32_t* bv = &wv[(tn8 >> 1) * 4 + (tn8 & 1) * 2];
                    mma16816(accm[tm][tn8], xf, bm);
                    mma16816(accv[tm][tn8], xs, bv);
                }
            }
        }
    }

    // ---------------- epilogue ----------------
    int ob = o0 + warp_n * 32 + 2 * (lane & 3);
    float2 bm2[4], bv2[4];
#pragma unroll
    for (int tn8 = 0; tn8 < 4; tn8++) {
        bm2[tn8] = *reinterpret_cast<const float2*>(&g_b_mean[ob + tn8 * 8]);
        bv2[tn8] = *reinterpret_cast<const float2*>(&g_b_var[ob + tn8 * 8]);
    }
    int mrow = m0 + warp_m * 64 + (lane >> 2);
#pragma unroll
    for (int tm = 0; tm < 4; tm++) {
        size_t r0 = (size_t)(mrow + tm * 16) * (2 * ODIM);
        size_t r8 = (size_t)(mrow + tm * 16 + 8) * (2 * ODIM);
#pragma unroll
        for (int tn8 = 0; tn8 < 4; tn8++) {
            int oc = ob + tn8 * 8;
            float2 v;
            v.x = accm[tm][tn8][0] + bm2[tn8].x;
            v.y = accm[tm][tn8][1] + bm2[tn8].y;
            *reinterpret_cast<float2*>(out + r0 + oc) = v;
            v.x = accm[tm][tn8][2] + bm2[tn8].x;
            v.y = accm[tm][tn8][3] + bm2[tn8].y;
            *reinterpret_cast<float2*>(out + r8 + oc) = v;
            v.x = accv[tm][tn8][0] + bv2[tn8].x;
            v.y = accv[tm][tn8][1] + bv2[tn8].y;
            *reinterpret_cast<float2*>(out + r0 + ODIM + oc) = v;
            v.x = accv[tm][tn8][2] + bv2[tn8].x;
            v.y = accv[tm][tn8][3] + bv2[tn8].y;
            *reinterpret_cast<float2*>(out + r8 + ODIM + oc) = v;
        }
    }
}

// ---------------- launch -----------------------------------------------------------
extern "C" void kernel_launch(void* const* d_in, const int* in_sizes, int n_in,
                              void* d_out, int out_size) {
    (void)in_sizes; (void)n_in; (void)out_size;
    const float* x  = (const float*)d_in[0];
    const float* Wl = (const float*)d_in[1];
    const float* bl = (const float*)d_in[2];
    float* out = (float*)d_out;

    prep_w_kernel<<<WELEMS / 4 / 256, 256>>>(Wl);   // 16384 blocks
    prep_x_kernel<<<XELEMS / 4 / 256, 256>>>(x);    // 8192 blocks
    prep_b_kernel<<<ODIM / 256, 256>>>(bl);         // 16 blocks

    cudaFuncSetAttribute(gemm_kernel, cudaFuncAttributeMaxDynamicSharedMemorySize, DYN_SMEM);
    gemm_kernel<<<dim3(NROWS / 128, ODIM / 128, 1), 256, DYN_SMEM>>>(out);
}

// round 5
// speedup vs baseline: 1.7569x; 1.0574x over previous
#include <cuda_runtime.h>
#include <cuda_fp16.h>
#include <cstdint>

#define NROWS 2048
#define KDIM  4096
#define ODIM  4096
#define WELEMS (ODIM * KDIM)       // 16,777,216
#define XELEMS (NROWS * KDIM)      // 8,388,608

// ---------------- scratch (static device globals; no runtime allocation) ----------
__device__ __align__(16) __half g_w_m[WELEMS];
__device__ __align__(16) __half g_w_v[WELEMS];
__device__ __align__(16) __half g_x[XELEMS];
__device__ __align__(16) float g_b_mean[ODIM];
__device__ __align__(16) float g_b_var[ODIM];

// ---------------- helpers ----------------------------------------------------------
__device__ __forceinline__ uint32_t smem_u32(const void* p) {
    uint32_t a;
    asm("{ .reg .u64 t; cvta.to.shared.u64 t, %1; cvt.u32.u64 %0, t; }" : "=r"(a) : "l"(p));
    return a;
}
__device__ __forceinline__ void cp16(uint32_t s, const void* g) {
    asm volatile("cp.async.cg.shared.global [%0], [%1], 16;\n" :: "r"(s), "l"(g));
}
#define CP_COMMIT() asm volatile("cp.async.commit_group;" ::: "memory")
#define CP_WAIT2()  asm volatile("cp.async.wait_group 2;" ::: "memory")

__device__ __forceinline__ void ldsm4(uint32_t* r, uint32_t addr) {
    asm volatile("ldmatrix.sync.aligned.m8n8.x4.shared.b16 {%0,%1,%2,%3}, [%4];"
                 : "=r"(r[0]), "=r"(r[1]), "=r"(r[2]), "=r"(r[3]) : "r"(addr));
}
__device__ __forceinline__ void mma16816(float* c, const uint32_t* a, const uint32_t* b) {
    asm volatile(
        "mma.sync.aligned.m16n8k16.row.col.f32.f16.f16.f32 "
        "{%0,%1,%2,%3}, {%4,%5,%6,%7}, {%8,%9}, {%0,%1,%2,%3};"
        : "+f"(c[0]), "+f"(c[1]), "+f"(c[2]), "+f"(c[3])
        : "r"(a[0]), "r"(a[1]), "r"(a[2]), "r"(a[3]), "r"(b[0]), "r"(b[1]));
}

// ---------------- prep kernels ----------------------------------------------------
__global__ void __launch_bounds__(256) prep_w_kernel(const float* __restrict__ Wl) {
    size_t i4 = (size_t)blockIdx.x * 256 + threadIdx.x;          // < 4,194,304
    float4 l0 = reinterpret_cast<const float4*>(Wl)[i4];
    float4 l1 = reinterpret_cast<const float4*>(Wl + (size_t)WELEMS)[i4];
    float4 l2 = reinterpret_cast<const float4*>(Wl + 2ull * WELEMS)[i4];
    const float* a0 = reinterpret_cast<const float*>(&l0);
    const float* a1 = reinterpret_cast<const float*>(&l1);
    const float* a2 = reinterpret_cast<const float*>(&l2);
    __half m[4], v[4];
#pragma unroll
    for (int j = 0; j < 4; j++) {
        float e0 = __expf(a0[j]), e1 = __expf(a1[j]), e2 = __expf(a2[j]);
        float inv = __frcp_rn(e0 + e1 + e2);
        float p0 = e0 * inv, p2 = e2 * inv;
        float mean = p2 - p0;
        float var  = (p2 + p0) - mean * mean;
        m[j] = __float2half_rn(mean);
        v[j] = __float2half_rn(var);
    }
    __half2* dm = reinterpret_cast<__half2*>(g_w_m);
    __half2* dv = reinterpret_cast<__half2*>(g_w_v);
    dm[2 * i4]     = __halves2half2(m[0], m[1]);
    dm[2 * i4 + 1] = __halves2half2(m[2], m[3]);
    dv[2 * i4]     = __halves2half2(v[0], v[1]);
    dv[2 * i4 + 1] = __halves2half2(v[2], v[3]);
}

__global__ void __launch_bounds__(256) prep_x_kernel(const float* __restrict__ x) {
    size_t i4 = (size_t)blockIdx.x * 256 + threadIdx.x;          // < 2,097,152
    float4 v = reinterpret_cast<const float4*>(x)[i4];
    const float* a = reinterpret_cast<const float*>(&v);
    __half h[4];
#pragma unroll
    for (int j = 0; j < 4; j++) h[j] = __float2half_rn(a[j]);
    __half2* dh = reinterpret_cast<__half2*>(g_x);
    dh[2 * i4]     = __halves2half2(h[0], h[1]);
    dh[2 * i4 + 1] = __halves2half2(h[2], h[3]);
}

__global__ void __launch_bounds__(256) prep_b_kernel(const float* __restrict__ bl) {
    int o = blockIdx.x * 256 + threadIdx.x;                      // < 4096
    float e0 = __expf(bl[o]);
    float e1 = __expf(bl[ODIM + o]);
    float e2 = __expf(bl[2 * ODIM + o]);
    float inv = __frcp_rn(e0 + e1 + e2);
    float p0 = e0 * inv, p2 = e2 * inv;
    float mean = p2 - p0;
    g_b_mean[o] = mean;
    g_b_var[o]  = (p2 + p0) - mean * mean;
}

// ---------------- GEMM kernel ------------------------------------------------------
// CTA tile: m=128 x o=128, K chunk = 64 fp16. 256 threads (8 warps, 2x4 warp grid,
// warp tile 64m x 32o). 3 smem tiles per stage (x | wm, wv), 4 stages, wait_group 2.
// x^2 fragments computed in registers (HMUL2) from the x fragment — no xs tile.
// Mean = X*WM ; Var = (X.X)*WV.  mma.sync.m16n8k16 f16 -> fp32.
#define TILE_B      16384                     // 128 rows * 128B (64 fp16)
#define STAGE_B     (3 * TILE_B)              // 49152
#define DYN_SMEM    (4 * STAGE_B)             // 196608

__global__ void __launch_bounds__(256, 1) gemm_kernel(float* __restrict__ out) {
    extern __shared__ char smem[];
    uint32_t sb = smem_u32(smem);
    int tid = threadIdx.x, wid = tid >> 5, lane = tid & 31;
    int warp_m = wid & 1;        // 0..1 -> 64-row half
    int warp_n = wid >> 1;       // 0..3 -> 32-col slice
    int m0 = blockIdx.x * 128;   // m fastest -> concurrent CTAs share w tiles in L2
    int o0 = blockIdx.y * 128;

    const __half* basep[3] = {
        g_x    + (size_t)m0 * KDIM,
        g_w_m  + (size_t)o0 * KDIM,
        g_w_v  + (size_t)o0 * KDIM,
    };

    // ---- cp.async store addressing (per thread, constant) ----
    const int ld_col = tid & 7;          // 16B column
    const int ld_tr  = tid >> 3;         // base row (0..31)
    const uint32_t ld_sw = ((uint32_t)(ld_col * 16)) ^ (((uint32_t)(ld_tr & 7)) << 4);

    auto load_chunk = [&](int chunk, int s) {
        uint32_t sbase = sb + (uint32_t)s * STAGE_B;
        int k0 = chunk * 64;
#pragma unroll
        for (int t = 0; t < 3; t++) {
            const __half* g = basep[t] + k0 + (size_t)ld_tr * KDIM + ld_col * 8;
            uint32_t tb = sbase + (uint32_t)t * TILE_B + (uint32_t)ld_tr * 128 + ld_sw;
#pragma unroll
            for (int it = 0; it < 4; it++) {
                cp16(tb + it * 32 * 128, g + (size_t)(it * 32) * KDIM);
            }
        }
    };

    // ---- ldmatrix addressing (per lane, constant pieces) ----
    const int a_row = warp_m * 64 + (lane & 15);
    const uint32_t a_rowoff = (uint32_t)a_row * 128;
    const uint32_t a_kb = (uint32_t)((lane >> 4) << 4);
    const uint32_t a_xor = ((uint32_t)(a_row & 7)) << 4;
    const int mi = lane >> 3;
    const int b_row = warp_n * 32 + ((mi & 2) << 2) + (lane & 7);
    const uint32_t b_rowoff = (uint32_t)b_row * 128;
    const uint32_t b_kb = (uint32_t)((mi & 1) << 4);
    const uint32_t b_xor = ((uint32_t)(b_row & 7)) << 4;

    float accm[4][4][4];   // [tm][tn8][4]
    float accv[4][4][4];
#pragma unroll
    for (int i = 0; i < 4; i++)
#pragma unroll
        for (int j = 0; j < 4; j++)
#pragma unroll
            for (int r = 0; r < 4; r++) { accm[i][j][r] = 0.f; accv[i][j][r] = 0.f; }

    load_chunk(0, 0); CP_COMMIT();
    load_chunk(1, 1); CP_COMMIT();
    load_chunk(2, 2); CP_COMMIT();

    for (int i = 0; i < 64; i++) {
        int s = i & 3;
        CP_WAIT2();                      // chunk i resident (i+1, i+2 may be in flight)
        __syncthreads();                 // all warps done computing chunk i-1 (stage (i+3)&3)

        if (i + 3 < 64) load_chunk(i + 3, (i + 3) & 3);
        CP_COMMIT();                     // always commit (empty at tail keeps accounting)

        uint32_t sbase = sb + (uint32_t)s * STAGE_B;
        uint32_t tX  = sbase;
        uint32_t tWM = sbase + TILE_B;
        uint32_t tWV = sbase + 2 * TILE_B;

#pragma unroll
        for (int kk = 0; kk < 4; kk++) {
            uint32_t ak = ((uint32_t)(kk * 32) + a_kb) ^ a_xor;
            uint32_t bk = ((uint32_t)(kk * 32) + b_kb) ^ b_xor;
            uint32_t wm[8], wv[8];
#pragma unroll
            for (int tn = 0; tn < 2; tn++) {
                uint32_t ro = b_rowoff + (uint32_t)(tn * 16 * 128) + bk;
                ldsm4(wm + tn * 4, tWM + ro);
                ldsm4(wv + tn * 4, tWV + ro);
            }
#pragma unroll
            for (int tm = 0; tm < 4; tm++) {
                uint32_t ro = a_rowoff + (uint32_t)(tm * 16 * 128) + ak;
                uint32_t xf[4], xs[4];
                ldsm4(xf, tX + ro);
#pragma unroll
                for (int j = 0; j < 4; j++) {
                    __half2 h = *reinterpret_cast<__half2*>(&xf[j]);
                    h = __hmul2(h, h);
                    xs[j] = *reinterpret_cast<uint32_t*>(&h);
                }
#pragma unroll
                for (int tn8 = 0; tn8 < 4; tn8++) {
                    const uint32_t* bm = &wm[(tn8 >> 1) * 4 + (tn8 & 1) * 2];
                    const uint32_t* bv = &wv[(tn8 >> 1) * 4 + (tn8 & 1) * 2];
                    mma16816(accm[tm][tn8], xf, bm);
                    mma16816(accv[tm][tn8], xs, bv);
                }
            }
        }
    }

    // ---------------- epilogue ----------------
    int ob = o0 + warp_n * 32 + 2 * (lane & 3);
    float2 bm2[4], bv2[4];
#pragma unroll
    for (int tn8 = 0; tn8 < 4; tn8++) {
        bm2[tn8] = *reinterpret_cast<const float2*>(&g_b_mean[ob + tn8 * 8]);
        bv2[tn8] = *reinterpret_cast<const float2*>(&g_b_var[ob + tn8 * 8]);
    }
    int mrow = m0 + warp_m * 64 + (lane >> 2);
#pragma unroll
    for (int tm = 0; tm < 4; tm++) {
        size_t r0 = (size_t)(mrow + tm * 16) * (2 * ODIM);
        size_t r8 = (size_t)(mrow + tm * 16 + 8) * (2 * ODIM);
#pragma unroll
        for (int tn8 = 0; tn8 < 4; tn8++) {
            int oc = ob + tn8 * 8;
            float2 v;
            v.x = accm[tm][tn8][0] + bm2[tn8].x;
            v.y = accm[tm][tn8][1] + bm2[tn8].y;
            *reinterpret_cast<float2*>(out + r0 + oc) = v;
            v.x = accm[tm][tn8][2] + bm2[tn8].x;
            v.y = accm[tm][tn8][3] + bm2[tn8].y;
            *reinterpret_cast<float2*>(out + r8 + oc) = v;
            v.x = accv[tm][tn8][0] + bv2[tn8].x;
            v.y = accv[tm][tn8][1] + bv2[tn8].y;
            *reinterpret_cast<float2*>(out + r0 + ODIM + oc) = v;
            v.x = accv[tm][tn8][2] + bv2[tn8].x;
            v.y = accv[tm][tn8][3] + bv2[tn8].y;
            *reinterpret_cast<float2*>(out + r8 + ODIM + oc) = v;
        }
    }
}

// ---------------- launch -----------------------------------------------------------
extern "C" void kernel_launch(void* const* d_in, const int* in_sizes, int n_in,
                              void* d_out, int out_size) {
    (void)in_sizes; (void)n_in; (void)out_size;
    const float* x  = (const float*)d_in[0];
    const float* Wl = (const float*)d_in[1];
    const float* bl = (const float*)d_in[2];
    float* out = (float*)d_out;

    prep_w_kernel<<<WELEMS / 4 / 256, 256>>>(Wl);   // 16384 blocks
    prep_x_kernel<<<XELEMS / 4 / 256, 256>>>(x);    // 8192 blocks
    prep_b_kernel<<<ODIM / 256, 256>>>(bl);         // 16 blocks

    cudaFuncSetAttribute(gemm_kernel, cudaFuncAttributeMaxDynamicSharedMemorySize, DYN_SMEM);
    gemm_kernel<<<dim3(NROWS / 128, ODIM / 128, 1), 256, DYN_SMEM>>>(out);
}

// round 6
// speedup vs baseline: 2.0649x; 1.1753x over previous
#include <cuda_runtime.h>
#include <cuda_fp16.h>
#include <cstdint>

#define NROWS 2048
#define KDIM  4096
#define ODIM  4096
#define WELEMS (ODIM * KDIM)       // 16,777,216
#define XELEMS (NROWS * KDIM)      // 8,388,608

// ---------------- scratch (static device globals; no runtime allocation) ----------
__device__ __align__(16) __half g_w_m[WELEMS];
__device__ __align__(16) __half g_w_v[WELEMS];
__device__ __align__(16) __half g_x[XELEMS];
__device__ __align__(16) float g_b_mean[ODIM];
__device__ __align__(16) float g_b_var[ODIM];

// ---------------- helpers ----------------------------------------------------------
__device__ __forceinline__ uint32_t smem_u32(const void* p) {
    uint32_t a;
    asm("{ .reg .u64 t; cvta.to.shared.u64 t, %1; cvt.u32.u64 %0, t; }" : "=r"(a) : "l"(p));
    return a;
}
__device__ __forceinline__ void cp16(uint32_t s, const void* g) {
    asm volatile("cp.async.cg.shared.global [%0], [%1], 16;\n" :: "r"(s), "l"(g));
}
// one arrive on mbar when ALL prior cp.async of this thread complete (.noinc: counts
// against the expected-arrival count)
__device__ __forceinline__ void cp_async_arrive(uint32_t mbar) {
    asm volatile("cp.async.mbarrier.arrive.noinc.shared.b64 [%0];" :: "r"(mbar) : "memory");
}
#define MBARRIER_INIT(addr, cnt) \
    asm volatile("mbarrier.init.shared.b64 [%0], %1;" :: "r"((uint32_t)(addr)), "r"((uint32_t)(cnt)) : "memory")
#define MBARRIER_ARRIVE(addr) \
    asm volatile("mbarrier.arrive.shared.b64 _, [%0];" :: "r"((uint32_t)(addr)) : "memory")

#define MBARRIER_WAIT_ACQ(mbar_smem_addr, phase_parity) do { \
    uint32_t _mbar = (uint32_t)(mbar_smem_addr); \
    uint32_t _parity = (uint32_t)(phase_parity); \
    uint32_t _done; \
    asm volatile( \
        "{\n\t.reg .pred p;\n\t" \
        "mbarrier.try_wait.parity.acquire.cta.shared::cta.b64 p, [%1], %2;\n\t" \
        "selp.b32 %0, 1, 0, p;\n\t}" \
        : "=r"(_done) : "r"(_mbar), "r"(_parity) : "memory"); \
    if (!_done) { \
        asm volatile( \
            "{\n\t.reg .pred P1;\n\t" \
            "WAIT_LOOP_%=:\n\t" \
            "mbarrier.try_wait.parity.acquire.cta.shared::cta.b64 P1, [%0], %1, 0x989680;\n\t" \
            "@P1 bra.uni WAIT_DONE_%=;\n\t" \
            "bra.uni WAIT_LOOP_%=;\n\t" \
            "WAIT_DONE_%=:\n\t}" \
            :: "r"(_mbar), "r"(_parity) : "memory"); \
    } \
} while (0)

#define MBARRIER_WAIT_RLX(mbar_smem_addr, phase_parity) do { \
    uint32_t _mbar = (uint32_t)(mbar_smem_addr); \
    uint32_t _parity = (uint32_t)(phase_parity); \
    uint32_t _done; \
    asm volatile( \
        "{\n\t.reg .pred p;\n\t" \
        "mbarrier.try_wait.parity.relaxed.cta.shared::cta.b64 p, [%1], %2, 0x989680;\n\t" \
        "selp.b32 %0, 1, 0, p;\n\t}" \
        : "=r"(_done) : "r"(_mbar), "r"(_parity) : "memory"); \
    if (!_done) { \
        asm volatile( \
            "{\n\t.reg .pred P1;\n\t" \
            "WAIT_LOOP_%=:\n\t" \
            "mbarrier.try_wait.parity.relaxed.cta.shared::cta.b64 P1, [%0], %1, 0x989680;\n\t" \
            "@P1 bra.uni WAIT_DONE_%=;\n\t" \
            "bra.uni WAIT_LOOP_%=;\n\t" \
            "WAIT_DONE_%=:\n\t}" \
            :: "r"(_mbar), "r"(_parity) : "memory"); \
    } \
} while (0)

__device__ __forceinline__ void ldsm4(uint32_t* r, uint32_t addr) {
    asm volatile("ldmatrix.sync.aligned.m8n8.x4.shared.b16 {%0,%1,%2,%3}, [%4];"
                 : "=r"(r[0]), "=r"(r[1]), "=r"(r[2]), "=r"(r[3]) : "r"(addr));
}
__device__ __forceinline__ void mma16816(float* c, const uint32_t* a, const uint32_t* b) {
    asm volatile(
        "mma.sync.aligned.m16n8k16.row.col.f32.f16.f16.f32 "
        "{%0,%1,%2,%3}, {%4,%5,%6,%7}, {%8,%9}, {%0,%1,%2,%3};"
        : "+f"(c[0]), "+f"(c[1]), "+f"(c[2]), "+f"(c[3])
        : "r"(a[0]), "r"(a[1]), "r"(a[2]), "r"(a[3]), "r"(b[0]), "r"(b[1]));
}

// ---------------- prep kernels ----------------------------------------------------
__global__ void __launch_bounds__(256) prep_w_kernel(const float* __restrict__ Wl) {
    size_t i4 = (size_t)blockIdx.x * 256 + threadIdx.x;          // < 4,194,304
    float4 l0 = reinterpret_cast<const float4*>(Wl)[i4];
    float4 l1 = reinterpret_cast<const float4*>(Wl + (size_t)WELEMS)[i4];
    float4 l2 = reinterpret_cast<const float4*>(Wl + 2ull * WELEMS)[i4];
    const float* a0 = reinterpret_cast<const float*>(&l0);
    const float* a1 = reinterpret_cast<const float*>(&l1);
    const float* a2 = reinterpret_cast<const float*>(&l2);
    __half m[4], v[4];
#pragma unroll
    for (int j = 0; j < 4; j++) {
        float e0 = __expf(a0[j]), e1 = __expf(a1[j]), e2 = __expf(a2[j]);
        float inv = __frcp_rn(e0 + e1 + e2);
        float p0 = e0 * inv, p2 = e2 * inv;
        float mean = p2 - p0;
        float var  = (p2 + p0) - mean * mean;
        m[j] = __float2half_rn(mean);
        v[j] = __float2half_rn(var);
    }
    __half2* dm = reinterpret_cast<__half2*>(g_w_m);
    __half2* dv = reinterpret_cast<__half2*>(g_w_v);
    dm[2 * i4]     = __halves2half2(m[0], m[1]);
    dm[2 * i4 + 1] = __halves2half2(m[2], m[3]);
    dv[2 * i4]     = __halves2half2(v[0], v[1]);
    dv[2 * i4 + 1] = __halves2half2(v[2], v[3]);
}

__global__ void __launch_bounds__(256) prep_x_kernel(const float* __restrict__ x) {
    size_t i4 = (size_t)blockIdx.x * 256 + threadIdx.x;          // < 2,097,152
    float4 v = reinterpret_cast<const float4*>(x)[i4];
    const float* a = reinterpret_cast<const float*>(&v);
    __half h[4];
#pragma unroll
    for (int j = 0; j < 4; j++) h[j] = __float2half_rn(a[j]);
    __half2* dh = reinterpret_cast<__half2*>(g_x);
    dh[2 * i4]     = __halves2half2(h[0], h[1]);
    dh[2 * i4 + 1] = __halves2half2(h[2], h[3]);
}

__global__ void __launch_bounds__(256) prep_b_kernel(const float* __restrict__ bl) {
    int o = blockIdx.x * 256 + threadIdx.x;                      // < 4096
    float e0 = __expf(bl[o]);
    float e1 = __expf(bl[ODIM + o]);
    float e2 = __expf(bl[2 * ODIM + o]);
    float inv = __frcp_rn(e0 + e1 + e2);
    float p0 = e0 * inv, p2 = e2 * inv;
    float mean = p2 - p0;
    g_b_mean[o] = mean;
    g_b_var[o]  = (p2 + p0) - mean * mean;
}

// ---------------- GEMM kernel ------------------------------------------------------
// CTA tile: m=128 x o=128, K chunk = 64 fp16. 256 threads (8 warps, 2x4 warp grid,
// warp tile 64m x 32o). 3 smem tiles per stage (x | wm, wv), 4-stage mbarrier
// producer/consumer ring — NO __syncthreads in the main loop; warp skew absorbed
// by stage slack. full[s]: 256 cp.async.noinc arrivals; empty[s]: 8 warp arrivals.
// Mean = X*WM ; Var = (X.X)*WV.  mma.sync.m16n8k16 f16 -> fp32.
#define TILE_B      16384                     // 128 rows * 128B (64 fp16)
#define STAGE_B     (3 * TILE_B)              // 49152
#define SM_FULL     0                         // 4 x 8B
#define SM_EMPTY    32                        // 4 x 8B
#define SM_TILES    1024
#define DYN_SMEM    (SM_TILES + 4 * STAGE_B)  // 197632
#define NCHUNK      64

__global__ void __launch_bounds__(256, 1) gemm_kernel(float* __restrict__ out) {
    extern __shared__ char smem[];
    uint32_t sb = smem_u32(smem);
    int tid = threadIdx.x, wid = tid >> 5, lane = tid & 31;
    int warp_m = wid & 1;        // 0..1 -> 64-row half
    int warp_n = wid >> 1;       // 0..3 -> 32-col slice
    int m0 = blockIdx.x * 128;   // m fastest -> concurrent CTAs share w tiles in L2
    int o0 = blockIdx.y * 128;

    if (tid == 0) {
#pragma unroll
        for (int s = 0; s < 4; s++) {
            MBARRIER_INIT(sb + SM_FULL + s * 8, 256);
            MBARRIER_INIT(sb + SM_EMPTY + s * 8, 8);
        }
    }
    __syncthreads();

    const __half* basep[3] = {
        g_x    + (size_t)m0 * KDIM,
        g_w_m  + (size_t)o0 * KDIM,
        g_w_v  + (size_t)o0 * KDIM,
    };

    // ---- cp.async store addressing (per thread, constant) ----
    const int ld_col = tid & 7;          // 16B column
    const int ld_tr  = tid >> 3;         // base row (0..31)
    const uint32_t ld_sw = ((uint32_t)(ld_col * 16)) ^ (((uint32_t)(ld_tr & 7)) << 4);

    auto load_chunk = [&](int chunk, int s) {
        uint32_t sbase = sb + SM_TILES + (uint32_t)s * STAGE_B;
        int k0 = chunk * 64;
#pragma unroll
        for (int t = 0; t < 3; t++) {
            const __half* g = basep[t] + k0 + (size_t)ld_tr * KDIM + ld_col * 8;
            uint32_t tb = sbase + (uint32_t)t * TILE_B + (uint32_t)ld_tr * 128 + ld_sw;
#pragma unroll
            for (int it = 0; it < 4; it++) {
                cp16(tb + it * 32 * 128, g + (size_t)(it * 32) * KDIM);
            }
        }
        cp_async_arrive(sb + SM_FULL + s * 8);   // arrive on full[s] at completion
    };

    // ---- ldmatrix addressing (per lane, constant pieces) ----
    const int a_row = warp_m * 64 + (lane & 15);
    const uint32_t a_rowoff = (uint32_t)a_row * 128;
    const uint32_t a_kb = (uint32_t)((lane >> 4) << 4);
    const uint32_t a_xor = ((uint32_t)(a_row & 7)) << 4;
    const int mi = lane >> 3;
    const int b_row = warp_n * 32 + ((mi & 2) << 2) + (lane & 7);
    const uint32_t b_rowoff = (uint32_t)b_row * 128;
    const uint32_t b_kb = (uint32_t)((mi & 1) << 4);
    const uint32_t b_xor = ((uint32_t)(b_row & 7)) << 4;

    float accm[4][4][4];   // [tm][tn8][4]
    float accv[4][4][4];
#pragma unroll
    for (int i = 0; i < 4; i++)
#pragma unroll
        for (int j = 0; j < 4; j++)
#pragma unroll
            for (int r = 0; r < 4; r++) { accm[i][j][r] = 0.f; accv[i][j][r] = 0.f; }

    // producer cursor: starts stage 0 / phase 1 (first waits pass immediately)
    int prod_stage = 0, prod_phase = 1;
    // consumer cursor: starts stage 0 / phase 0
    int cons_stage = 0, cons_phase = 0;

    // prologue: fill stages 0..2 with chunks 0..2
#pragma unroll
    for (int p = 0; p < 3; p++) {
        MBARRIER_WAIT_RLX(sb + SM_EMPTY + prod_stage * 8, prod_phase);
        load_chunk(p, prod_stage);
        if (++prod_stage == 4) { prod_stage = 0; prod_phase ^= 1; }
    }

    for (int i = 0; i < NCHUNK; i++) {
        // ---- consume chunk i ----
        MBARRIER_WAIT_ACQ(sb + SM_FULL + cons_stage * 8, cons_phase);

        uint32_t sbase = sb + SM_TILES + (uint32_t)cons_stage * STAGE_B;
        uint32_t tX  = sbase;
        uint32_t tWM = sbase + TILE_B;
        uint32_t tWV = sbase + 2 * TILE_B;

#pragma unroll
        for (int kk = 0; kk < 4; kk++) {
            uint32_t ak = ((uint32_t)(kk * 32) + a_kb) ^ a_xor;
            uint32_t bk = ((uint32_t)(kk * 32) + b_kb) ^ b_xor;
            uint32_t wm[8], wv[8];
#pragma unroll
            for (int tn = 0; tn < 2; tn++) {
                uint32_t ro = b_rowoff + (uint32_t)(tn * 16 * 128) + bk;
                ldsm4(wm + tn * 4, tWM + ro);
                ldsm4(wv + tn * 4, tWV + ro);
            }
#pragma unroll
            for (int tm = 0; tm < 4; tm++) {
                uint32_t ro = a_rowoff + (uint32_t)(tm * 16 * 128) + ak;
                uint32_t xf[4], xs[4];
                ldsm4(xf, tX + ro);
#pragma unroll
                for (int j = 0; j < 4; j++) {
                    __half2 h = *reinterpret_cast<__half2*>(&xf[j]);
                    h = __hmul2(h, h);
                    xs[j] = *reinterpret_cast<uint32_t*>(&h);
                }
#pragma unroll
                for (int tn8 = 0; tn8 < 4; tn8++) {
                    const uint32_t* bm = &wm[(tn8 >> 1) * 4 + (tn8 & 1) * 2];
                    const uint32_t* bv = &wv[(tn8 >> 1) * 4 + (tn8 & 1) * 2];
                    mma16816(accm[tm][tn8], xf, bm);
                    mma16816(accv[tm][tn8], xs, bv);
                }
            }
        }

        // this warp is done reading stage cons_stage
        if (lane == 0) MBARRIER_ARRIVE(sb + SM_EMPTY + cons_stage * 8);
        if (++cons_stage == 4) { cons_stage = 0; cons_phase ^= 1; }

        // ---- produce chunk i+3 ----
        if (i + 3 < NCHUNK) {
            MBARRIER_WAIT_RLX(sb + SM_EMPTY + prod_stage * 8, prod_phase);
            load_chunk(i + 3, prod_stage);
            if (++prod_stage == 4) { prod_stage = 0; prod_phase ^= 1; }
        }
    }

    // ---------------- epilogue ----------------
    int ob = o0 + warp_n * 32 + 2 * (lane & 3);
    float2 bm2[4], bv2[4];
#pragma unroll
    for (int tn8 = 0; tn8 < 4; tn8++) {
        bm2[tn8] = *reinterpret_cast<const float2*>(&g_b_mean[ob + tn8 * 8]);
        bv2[tn8] = *reinterpret_cast<const float2*>(&g_b_var[ob + tn8 * 8]);
    }
    int mrow = m0 + warp_m * 64 + (lane >> 2);
#pragma unroll
    for (int tm = 0; tm < 4; tm++) {
        size_t r0 = (size_t)(mrow + tm * 16) * (2 * ODIM);
        size_t r8 = (size_t)(mrow + tm * 16 + 8) * (2 * ODIM);
#pragma unroll
        for (int tn8 = 0; tn8 < 4; tn8++) {
            int oc = ob + tn8 * 8;
            float2 v;
            v.x = accm[tm][tn8][0] + bm2[tn8].x;
            v.y = accm[tm][tn8][1] + bm2[tn8].y;
            *reinterpret_cast<float2*>(out + r0 + oc) = v;
            v.x = accm[tm][tn8][2] + bm2[tn8].x;
            v.y = accm[tm][tn8][3] + bm2[tn8].y;
            *reinterpret_cast<float2*>(out + r8 + oc) = v;
            v.x = accv[tm][tn8][0] + bv2[tn8].x;
            v.y = accv[tm][tn8][1] + bv2[tn8].y;
            *reinterpret_cast<float2*>(out + r0 + ODIM + oc) = v;
            v.x = accv[tm][tn8][2] + bv2[tn8].x;
            v.y = accv[tm][tn8][3] + bv2[tn8].y;
            *reinterpret_cast<float2*>(out + r8 + ODIM + oc) = v;
        }
    }
}

// ---------------- launch -----------------------------------------------------------
extern "C" void kernel_launch(void* const* d_in, const int* in_sizes, int n_in,
                              void* d_out, int out_size) {
    (void)in_sizes; (void)n_in; (void)out_size;
    const float* x  = (const float*)d_in[0];
    const float* Wl = (const float*)d_in[1];
    const float* bl = (const float*)d_in[2];
    float* out = (float*)d_out;

    prep_w_kernel<<<WELEMS / 4 / 256, 256>>>(Wl);   // 16384 blocks
    prep_x_kernel<<<XELEMS / 4 / 256, 256>>>(x);    // 8192 blocks
    prep_b_kernel<<<ODIM / 256, 256>>>(bl);         // 16 blocks

    cudaFuncSetAttribute(gemm_kernel, cudaFuncAttributeMaxDynamicSharedMemorySize, DYN_SMEM);
    gemm_kernel<<<dim3(NROWS / 128, ODIM / 128, 1), 256, DYN_SMEM>>>(out);
}